// round 8
// baseline (speedup 1.0000x reference)
#include <cuda_runtime.h>
#include <cuda_bf16.h>
#include <cstdint>

#define B_  8
#define T_  2048
#define NH  4
#define HD  32
#define CE  128
#define QKVS 384
#define NTOK (B_ * T_)

// softmax scale * log2(e)
#define SC2 (0.17677669529663687f * 1.4426950408889634f)

// ---------------------------------------------------------------------------
// Device-global scratch
// ---------------------------------------------------------------------------
__device__ float g_qkv[(size_t)NTOK * QKVS];   // fp32 [tok][384] (R5 layout)
__device__ float g_y[(size_t)NTOK * CE];       // fp32 [tok][128]
__device__ __nv_bfloat16 g_qh[(size_t)NTOK * CE], g_ql[(size_t)NTOK * CE];
__device__ __nv_bfloat16 g_kh[(size_t)NTOK * CE], g_kl[(size_t)NTOK * CE];
__device__ __nv_bfloat16 g_vh[(size_t)NTOK * CE], g_vl[(size_t)NTOK * CE];

// ---------------------------------------------------------------------------
// helpers (R5 verbatim)
// ---------------------------------------------------------------------------
__device__ __forceinline__ uint32_t smem_u32(const void* p) {
    return (uint32_t)__cvta_generic_to_shared(p);
}
__device__ __forceinline__ void ldmx4(uint32_t& r0, uint32_t& r1, uint32_t& r2,
                                      uint32_t& r3, uint32_t addr) {
    asm volatile("ldmatrix.sync.aligned.m8n8.x4.shared.b16 {%0,%1,%2,%3}, [%4];"
                 : "=r"(r0), "=r"(r1), "=r"(r2), "=r"(r3) : "r"(addr));
}
__device__ __forceinline__ void ldmx4t(uint32_t& r0, uint32_t& r1, uint32_t& r2,
                                       uint32_t& r3, uint32_t addr) {
    asm volatile("ldmatrix.sync.aligned.m8n8.x4.trans.shared.b16 {%0,%1,%2,%3}, [%4];"
                 : "=r"(r0), "=r"(r1), "=r"(r2), "=r"(r3) : "r"(addr));
}
__device__ __forceinline__ void mma16816(float (&c)[4], const uint32_t (&a)[4],
                                         uint32_t b0, uint32_t b1) {
    asm volatile(
        "mma.sync.aligned.m16n8k16.row.col.f32.bf16.bf16.f32 "
        "{%0,%1,%2,%3}, {%4,%5,%6,%7}, {%8,%9}, {%0,%1,%2,%3};"
        : "+f"(c[0]), "+f"(c[1]), "+f"(c[2]), "+f"(c[3])
        : "r"(a[0]), "r"(a[1]), "r"(a[2]), "r"(a[3]), "r"(b0), "r"(b1));
}
__device__ __forceinline__ float ex2f(float x) {
    float r; asm("ex2.approx.f32 %0, %1;" : "=f"(r) : "f"(x)); return r;
}
__device__ __forceinline__ uint32_t packbf(float a, float b) {
    __nv_bfloat162 t = __floats2bfloat162_rn(a, b);
    return *reinterpret_cast<uint32_t*>(&t);
}
__device__ __forceinline__ void split2pack(float a, float b,
                                           __nv_bfloat16* ph, __nv_bfloat16* pl) {
    __nv_bfloat162 hi = __floats2bfloat162_rn(a, b);
    *reinterpret_cast<__nv_bfloat162*>(ph) = hi;
    float ra = a - __bfloat162float(__low2bfloat16(hi));
    float rb = b - __bfloat162float(__high2bfloat16(hi));
    *reinterpret_cast<__nv_bfloat162*>(pl) = __floats2bfloat162_rn(ra, rb);
}
__device__ __forceinline__ float bfres(float a) {
    return a - __bfloat162float(__float2bfloat16(a));
}

// ---------------------------------------------------------------------------
// GEMM via bf16 mma (R5 VERBATIM — in-kernel hi/lo split from fp32).
// 256 threads, BM=128, BN=64, BK=32.
// MODE 0: A = param (x),  C = g_qkv     MODE 1: A = g_y, C = param (out)
// ---------------------------------------------------------------------------
template <int MODE>
__global__ __launch_bounds__(256) void gemm_mma(
    const float* __restrict__ Ap, const float* __restrict__ W,
    const float* __restrict__ bias, float* __restrict__ Cp, int N)
{
    const float* A = (MODE == 0) ? Ap : g_y;
    float*       C = (MODE == 0) ? g_qkv : Cp;
    const int K = CE;

    __shared__ __nv_bfloat16 Ah[128 * 40], Al[128 * 40];  // [row][k] pad 40
    __shared__ __nv_bfloat16 Wh[32 * 72],  Wl[32 * 72];   // [k][n]  pad 72

    const int tid = threadIdx.x;
    const int w   = tid >> 5;
    const int l   = tid & 31;
    const int bm0 = blockIdx.x * 128;
    const int bn0 = blockIdx.y * 64;

    float acc[8][4];
    #pragma unroll
    for (int i = 0; i < 8; i++)
        #pragma unroll
        for (int j = 0; j < 4; j++) acc[i][j] = 0.f;

    for (int k0 = 0; k0 < 128; k0 += 32) {
        if (k0) __syncthreads();
        // A chunk 128x32: 1024 float4
        #pragma unroll
        for (int it = 0; it < 4; it++) {
            int fid = tid + it * 256;
            int r = fid >> 3, c4 = (fid & 7) << 2;
            float4 v = *(const float4*)(A + (size_t)(bm0 + r) * K + k0 + c4);
            split2pack(v.x, v.y, &Ah[r * 40 + c4],     &Al[r * 40 + c4]);
            split2pack(v.z, v.w, &Ah[r * 40 + c4 + 2], &Al[r * 40 + c4 + 2]);
        }
        // W chunk 32x64: 512 float4
        #pragma unroll
        for (int it = 0; it < 2; it++) {
            int fid = tid + it * 256;
            int r = fid >> 4, c4 = (fid & 15) << 2;
            float4 v = *(const float4*)(W + (size_t)(k0 + r) * N + bn0 + c4);
            split2pack(v.x, v.y, &Wh[r * 72 + c4],     &Wl[r * 72 + c4]);
            split2pack(v.z, v.w, &Wh[r * 72 + c4 + 2], &Wl[r * 72 + c4 + 2]);
        }
        __syncthreads();

        uint32_t ahf[2][4], alf[2][4];
        #pragma unroll
        for (int ks2 = 0; ks2 < 2; ks2++) {
            int off = (w * 16 + (l & 7) + ((l >> 3) & 1) * 8) * 40
                      + ks2 * 16 + ((l >> 4) & 1) * 8;
            ldmx4(ahf[ks2][0], ahf[ks2][1], ahf[ks2][2], ahf[ks2][3], smem_u32(&Ah[off]));
            ldmx4(alf[ks2][0], alf[ks2][1], alf[ks2][2], alf[ks2][3], smem_u32(&Al[off]));
        }
        #pragma unroll
        for (int ks2 = 0; ks2 < 2; ks2++) {
            #pragma unroll
            for (int np = 0; np < 4; np++) {
                int off = (ks2 * 16 + ((l >> 3) & 1) * 8 + (l & 7)) * 72
                          + np * 16 + ((l >> 4) & 1) * 8;
                uint32_t wh0, wh1, wh2, wh3, wl0, wl1, wl2, wl3;
                ldmx4t(wh0, wh1, wh2, wh3, smem_u32(&Wh[off]));
                ldmx4t(wl0, wl1, wl2, wl3, smem_u32(&Wl[off]));
                mma16816(acc[2 * np],     ahf[ks2], wh0, wh1);
                mma16816(acc[2 * np],     ahf[ks2], wl0, wl1);
                mma16816(acc[2 * np],     alf[ks2], wh0, wh1);
                mma16816(acc[2 * np + 1], ahf[ks2], wh2, wh3);
                mma16816(acc[2 * np + 1], ahf[ks2], wl2, wl3);
                mma16816(acc[2 * np + 1], alf[ks2], wh2, wh3);
            }
        }
    }

    const int g = l >> 2, j2 = (l & 3) * 2;
    #pragma unroll
    for (int nt = 0; nt < 8; nt++) {
        int n = bn0 + nt * 8 + j2;
        float b0 = bias[n], b1 = bias[n + 1];
        float* p0 = C + (size_t)(bm0 + w * 16 + g) * N + n;
        float* p1 = C + (size_t)(bm0 + w * 16 + 8 + g) * N + n;
        *(float2*)p0 = make_float2(acc[nt][0] + b0, acc[nt][1] + b1);
        *(float2*)p1 = make_float2(acc[nt][2] + b0, acc[nt][3] + b1);
    }
}

// ---------------------------------------------------------------------------
// NEW (trivial): split fp32 g_qkv -> bf16 hi/lo q/k/v arrays, q pre-scaled.
// One thread per float2. NTOK*192 threads exactly.
// ---------------------------------------------------------------------------
__global__ __launch_bounds__(256) void qkv_split_kernel()
{
    size_t i = (size_t)blockIdx.x * 256 + threadIdx.x;   // < NTOK*192
    size_t tok = i / 192;
    int    p   = (int)(i % 192);
    int    c2  = p * 2;            // 0..382 (even)
    float2 v = *(const float2*)(g_qkv + tok * QKVS + c2);
    int sect = c2 >> 7;            // 0=q 1=k 2=v
    int col  = c2 & 127;
    __nv_bfloat16 *dh, *dl;
    float mul;
    if (sect == 0)      { dh = g_qh; dl = g_ql; mul = SC2; }
    else if (sect == 1) { dh = g_kh; dl = g_kl; mul = 1.f; }
    else                { dh = g_vh; dl = g_vl; mul = 1.f; }
    split2pack(v.x * mul, v.y * mul, dh + tok * CE + col, dl + tok * CE + col);
}

// ---------------------------------------------------------------------------
// Flash attention (R5 compute structure verbatim; staging = plain uint4
// copies of pre-split bf16 data; epilogue = R5 fp32 g_y write).
// 128 threads (4 warps x 16 query rows), Q tile 64, KV tile 64.
// ---------------------------------------------------------------------------
__global__ __launch_bounds__(128) void attn_mma()
{
    __shared__ __nv_bfloat16 Qh[64 * 40], Ql[64 * 40];
    __shared__ __nv_bfloat16 Kh[64 * 40], Kl[64 * 40];
    __shared__ __nv_bfloat16 Vh[64 * 40], Vl[64 * 40];

    const int tid = threadIdx.x;
    const int w   = tid >> 5;
    const int l   = tid & 31;
    const int qt  = gridDim.x - 1 - blockIdx.x;   // heavy tiles first
    const int hh  = blockIdx.y;
    const int b   = blockIdx.z;
    const int qr0 = qt * 64;
    const int bT  = b * T_;
    const int hoff = hh * HD;

    // Load Q tile (pre-scaled hi/lo) into smem
    #pragma unroll
    for (int it = 0; it < 2; it++) {
        int fid = tid + it * 128;
        int r = fid >> 2, j = fid & 3;
        size_t gp = (size_t)(bT + qr0 + r) * CE + hoff + j * 8;
        *(uint4*)(Qh + r * 40 + j * 8) = *(const uint4*)(g_qh + gp);
        *(uint4*)(Ql + r * 40 + j * 8) = *(const uint4*)(g_ql + gp);
    }
    __syncthreads();

    // Q fragments persist in registers (2 k-steps x hi/lo)
    uint32_t qh[2][4], ql[2][4];
    #pragma unroll
    for (int ks2 = 0; ks2 < 2; ks2++) {
        int off = (w * 16 + (l & 7) + ((l >> 3) & 1) * 8) * 40
                  + ks2 * 16 + ((l >> 4) & 1) * 8;
        ldmx4(qh[ks2][0], qh[ks2][1], qh[ks2][2], qh[ks2][3], smem_u32(&Qh[off]));
        ldmx4(ql[ks2][0], ql[ks2][1], ql[ks2][2], ql[ks2][3], smem_u32(&Ql[off]));
    }

    float m2[2] = {-1e30f, -1e30f}, li[2] = {0.f, 0.f};
    float o[4][4];
    #pragma unroll
    for (int i = 0; i < 4; i++)
        #pragma unroll
        for (int j = 0; j < 4; j++) o[i][j] = 0.f;

    const int row0 = qr0 + w * 16 + (l >> 2);
    const int row1 = row0 + 8;

    for (int kt = 0; kt <= qt; kt++) {
        const int kn0 = kt * 64;
        __syncthreads();
        // Stage K & V hi/lo (plain copies; already split)
        #pragma unroll
        for (int it = 0; it < 2; it++) {
            int fid = tid + it * 128;
            int r = fid >> 2, j = fid & 3;
            size_t gp = (size_t)(bT + kn0 + r) * CE + hoff + j * 8;
            *(uint4*)(Kh + r * 40 + j * 8) = *(const uint4*)(g_kh + gp);
            *(uint4*)(Kl + r * 40 + j * 8) = *(const uint4*)(g_kl + gp);
            *(uint4*)(Vh + r * 40 + j * 8) = *(const uint4*)(g_vh + gp);
            *(uint4*)(Vl + r * 40 + j * 8) = *(const uint4*)(g_vl + gp);
        }
        __syncthreads();

        // ---- S = Q @ K^T (log2 units; scale pre-folded into Q) ----
        float s[8][4];
        #pragma unroll
        for (int i = 0; i < 8; i++)
            #pragma unroll
            for (int j = 0; j < 4; j++) s[i][j] = 0.f;

        #pragma unroll
        for (int ks2 = 0; ks2 < 2; ks2++) {
            #pragma unroll
            for (int np = 0; np < 4; np++) {
                int off = (np * 16 + ((l >> 4) & 1) * 8 + (l & 7)) * 40
                          + ks2 * 16 + ((l >> 3) & 1) * 8;
                uint32_t kh0, kh1, kh2, kh3, kl0, kl1, kl2, kl3;
                ldmx4(kh0, kh1, kh2, kh3, smem_u32(&Kh[off]));
                ldmx4(kl0, kl1, kl2, kl3, smem_u32(&Kl[off]));
                mma16816(s[2 * np],     qh[ks2], kh0, kh1);
                mma16816(s[2 * np],     qh[ks2], kl0, kl1);
                mma16816(s[2 * np],     ql[ks2], kh0, kh1);
                mma16816(s[2 * np + 1], qh[ks2], kh2, kh3);
                mma16816(s[2 * np + 1], qh[ks2], kl2, kl3);
                mma16816(s[2 * np + 1], ql[ks2], kh2, kh3);
            }
        }

        // ---- causal mask (diagonal tile only) ----
        if (kt == qt) {
            #pragma unroll
            for (int nt = 0; nt < 8; nt++) {
                int c = kn0 + nt * 8 + (l & 3) * 2;
                if (c > row0)     s[nt][0] = -1e30f;
                if (c + 1 > row0) s[nt][1] = -1e30f;
                if (c > row1)     s[nt][2] = -1e30f;
                if (c + 1 > row1) s[nt][3] = -1e30f;
            }
        }

        // ---- online softmax (base 2) ----
        float mx0 = -1e30f, mx1 = -1e30f;
        #pragma unroll
        for (int nt = 0; nt < 8; nt++) {
            mx0 = fmaxf(mx0, fmaxf(s[nt][0], s[nt][1]));
            mx1 = fmaxf(mx1, fmaxf(s[nt][2], s[nt][3]));
        }
        mx0 = fmaxf(mx0, __shfl_xor_sync(0xffffffffu, mx0, 1));
        mx0 = fmaxf(mx0, __shfl_xor_sync(0xffffffffu, mx0, 2));
        mx1 = fmaxf(mx1, __shfl_xor_sync(0xffffffffu, mx1, 1));
        mx1 = fmaxf(mx1, __shfl_xor_sync(0xffffffffu, mx1, 2));
        float mn0 = fmaxf(m2[0], mx0), mn1 = fmaxf(m2[1], mx1);
        float al0 = ex2f(m2[0] - mn0), al1 = ex2f(m2[1] - mn1);
        m2[0] = mn0; m2[1] = mn1;
        float rs0 = 0.f, rs1 = 0.f;
        #pragma unroll
        for (int nt = 0; nt < 8; nt++) {
            s[nt][0] = ex2f(s[nt][0] - mn0);
            s[nt][1] = ex2f(s[nt][1] - mn0);
            s[nt][2] = ex2f(s[nt][2] - mn1);
            s[nt][3] = ex2f(s[nt][3] - mn1);
            rs0 += s[nt][0] + s[nt][1];
            rs1 += s[nt][2] + s[nt][3];
        }
        rs0 += __shfl_xor_sync(0xffffffffu, rs0, 1);
        rs0 += __shfl_xor_sync(0xffffffffu, rs0, 2);
        rs1 += __shfl_xor_sync(0xffffffffu, rs1, 1);
        rs1 += __shfl_xor_sync(0xffffffffu, rs1, 2);
        li[0] = li[0] * al0 + rs0;
        li[1] = li[1] * al1 + rs1;
        #pragma unroll
        for (int nt = 0; nt < 4; nt++) {
            o[nt][0] *= al0; o[nt][1] *= al0;
            o[nt][2] *= al1; o[nt][3] *= al1;
        }

        // ---- O += P @ V (P from registers, 3-term hi/lo) ----
        #pragma unroll
        for (int kk = 0; kk < 4; kk++) {
            uint32_t ah[4], alr[4];
            ah[0]  = packbf(s[2 * kk][0], s[2 * kk][1]);
            ah[1]  = packbf(s[2 * kk][2], s[2 * kk][3]);
            ah[2]  = packbf(s[2 * kk + 1][0], s[2 * kk + 1][1]);
            ah[3]  = packbf(s[2 * kk + 1][2], s[2 * kk + 1][3]);
            alr[0] = packbf(bfres(s[2 * kk][0]), bfres(s[2 * kk][1]));
            alr[1] = packbf(bfres(s[2 * kk][2]), bfres(s[2 * kk][3]));
            alr[2] = packbf(bfres(s[2 * kk + 1][0]), bfres(s[2 * kk + 1][1]));
            alr[3] = packbf(bfres(s[2 * kk + 1][2]), bfres(s[2 * kk + 1][3]));
            #pragma unroll
            for (int np = 0; np < 2; np++) {
                int off = (kk * 16 + ((l >> 3) & 1) * 8 + (l & 7)) * 40
                          + np * 16 + ((l >> 4) & 1) * 8;
                uint32_t vh0, vh1, vh2, vh3, vl0, vl1, vl2, vl3;
                ldmx4t(vh0, vh1, vh2, vh3, smem_u32(&Vh[off]));
                ldmx4t(vl0, vl1, vl2, vl3, smem_u32(&Vl[off]));
                mma16816(o[2 * np],     ah,  vh0, vh1);
                mma16816(o[2 * np],     ah,  vl0, vl1);
                mma16816(o[2 * np],     alr, vh0, vh1);
                mma16816(o[2 * np + 1], ah,  vh2, vh3);
                mma16816(o[2 * np + 1], ah,  vl2, vl3);
                mma16816(o[2 * np + 1], alr, vh2, vh3);
            }
        }
    }

    // ---- epilogue: normalize, write fp32 y (R5 verbatim) ----
    float inv0 = 1.f / li[0], inv1 = 1.f / li[1];
    size_t yb0 = (size_t)(bT + row0) * CE + hoff;
    size_t yb1 = yb0 + (size_t)8 * CE;
    #pragma unroll
    for (int nt = 0; nt < 4; nt++) {
        int d = nt * 8 + (l & 3) * 2;
        *(float2*)(g_y + yb0 + d) = make_float2(o[nt][0] * inv0, o[nt][1] * inv0);
        *(float2*)(g_y + yb1 + d) = make_float2(o[nt][2] * inv1, o[nt][3] * inv1);
    }
}

// ---------------------------------------------------------------------------
extern "C" void kernel_launch(void* const* d_in, const int* in_sizes, int n_in,
                              void* d_out, int out_size)
{
    const float* x      = (const float*)d_in[0];
    const float* w_qkv  = (const float*)d_in[1];
    const float* b_qkv  = (const float*)d_in[2];
    const float* w_proj = (const float*)d_in[3];
    const float* b_proj = (const float*)d_in[4];
    float* out = (float*)d_out;

    // 1) qkv = x @ w_qkv + b_qkv -> g_qkv (fp32, R5 path)
    gemm_mma<0><<<dim3(NTOK / 128, QKVS / 64), 256>>>(x, w_qkv, b_qkv, nullptr, QKVS);

    // 1b) split qkv -> bf16 hi/lo q/k/v (q pre-scaled)
    qkv_split_kernel<<<(unsigned)((size_t)NTOK * 192 / 256), 256>>>();

    // 2) attention -> g_y (fp32)
    attn_mma<<<dim3(T_ / 64, NH, B_), 128>>>();

    // 3) out = g_y @ w_proj + b_proj (R5 path)
    gemm_mma<1><<<dim3(NTOK / 128, CE / 64), 256>>>(nullptr, w_proj, b_proj, out, CE);
}

// round 9
// speedup vs baseline: 1.0248x; 1.0248x over previous
#include <cuda_runtime.h>
#include <cuda_bf16.h>
#include <cstdint>

#define B_  8
#define T_  2048
#define NH  4
#define HD  32
#define CE  128
#define QKVS 384
#define NTOK (B_ * T_)

// softmax scale * log2(e)
#define SC2 (0.17677669529663687f * 1.4426950408889634f)

// ---------------------------------------------------------------------------
// Device-global scratch
// ---------------------------------------------------------------------------
__device__ float g_y[(size_t)NTOK * CE];       // fp32 [tok][128]
__device__ __nv_bfloat16 g_qh[(size_t)NTOK * CE], g_ql[(size_t)NTOK * CE];
__device__ __nv_bfloat16 g_kh[(size_t)NTOK * CE], g_kl[(size_t)NTOK * CE];
__device__ __nv_bfloat16 g_vh[(size_t)NTOK * CE], g_vl[(size_t)NTOK * CE];

// ---------------------------------------------------------------------------
// helpers
// ---------------------------------------------------------------------------
__device__ __forceinline__ uint32_t smem_u32(const void* p) {
    return (uint32_t)__cvta_generic_to_shared(p);
}
__device__ __forceinline__ void ldmx4(uint32_t& r0, uint32_t& r1, uint32_t& r2,
                                      uint32_t& r3, uint32_t addr) {
    asm volatile("ldmatrix.sync.aligned.m8n8.x4.shared.b16 {%0,%1,%2,%3}, [%4];"
                 : "=r"(r0), "=r"(r1), "=r"(r2), "=r"(r3) : "r"(addr));
}
__device__ __forceinline__ void ldmx4t(uint32_t& r0, uint32_t& r1, uint32_t& r2,
                                       uint32_t& r3, uint32_t addr) {
    asm volatile("ldmatrix.sync.aligned.m8n8.x4.trans.shared.b16 {%0,%1,%2,%3}, [%4];"
                 : "=r"(r0), "=r"(r1), "=r"(r2), "=r"(r3) : "r"(addr));
}
__device__ __forceinline__ void mma16816(float (&c)[4], const uint32_t (&a)[4],
                                         uint32_t b0, uint32_t b1) {
    asm volatile(
        "mma.sync.aligned.m16n8k16.row.col.f32.bf16.bf16.f32 "
        "{%0,%1,%2,%3}, {%4,%5,%6,%7}, {%8,%9}, {%0,%1,%2,%3};"
        : "+f"(c[0]), "+f"(c[1]), "+f"(c[2]), "+f"(c[3])
        : "r"(a[0]), "r"(a[1]), "r"(a[2]), "r"(a[3]), "r"(b0), "r"(b1));
}
__device__ __forceinline__ float ex2f(float x) {
    float r; asm("ex2.approx.f32 %0, %1;" : "=f"(r) : "f"(x)); return r;
}
__device__ __forceinline__ uint32_t packbf(float a, float b) {
    __nv_bfloat162 t = __floats2bfloat162_rn(a, b);
    return *reinterpret_cast<uint32_t*>(&t);
}
__device__ __forceinline__ void split2pack(float a, float b,
                                           __nv_bfloat16* ph, __nv_bfloat16* pl) {
    __nv_bfloat162 hi = __floats2bfloat162_rn(a, b);
    *reinterpret_cast<__nv_bfloat162*>(ph) = hi;
    float ra = a - __bfloat162float(__low2bfloat16(hi));
    float rb = b - __bfloat162float(__high2bfloat16(hi));
    *reinterpret_cast<__nv_bfloat162*>(pl) = __floats2bfloat162_rn(ra, rb);
}
__device__ __forceinline__ float bfres(float a) {
    return a - __bfloat162float(__float2bfloat16(a));
}
__device__ __forceinline__ void cp16(uint32_t dst, const void* src) {
    asm volatile("cp.async.cg.shared.global [%0], [%1], 16;" :: "r"(dst), "l"(src)
                 : "memory");
}

// ---------------------------------------------------------------------------
// GEMM via bf16 mma (R8 body verbatim; MODE 0 epilogue now fuses the
// q/k/v hi/lo split — numerically identical to qkv_split(gemm output)).
// 256 threads, BM=128, BN=64, BK=32.
// MODE 0: A = param (x),  C -> g_q/g_k/g_v hi/lo    MODE 1: A = g_y, C = out
// ---------------------------------------------------------------------------
template <int MODE>
__global__ __launch_bounds__(256) void gemm_mma(
    const float* __restrict__ Ap, const float* __restrict__ W,
    const float* __restrict__ bias, float* __restrict__ Cp, int N)
{
    const float* A = (MODE == 0) ? Ap : g_y;
    const int K = CE;

    __shared__ __nv_bfloat16 Ah[128 * 40], Al[128 * 40];  // [row][k] pad 40
    __shared__ __nv_bfloat16 Wh[32 * 72],  Wl[32 * 72];   // [k][n]  pad 72

    const int tid = threadIdx.x;
    const int w   = tid >> 5;
    const int l   = tid & 31;
    const int bm0 = blockIdx.x * 128;
    const int bn0 = blockIdx.y * 64;

    float acc[8][4];
    #pragma unroll
    for (int i = 0; i < 8; i++)
        #pragma unroll
        for (int j = 0; j < 4; j++) acc[i][j] = 0.f;

    for (int k0 = 0; k0 < 128; k0 += 32) {
        if (k0) __syncthreads();
        // A chunk 128x32: 1024 float4
        #pragma unroll
        for (int it = 0; it < 4; it++) {
            int fid = tid + it * 256;
            int r = fid >> 3, c4 = (fid & 7) << 2;
            float4 v = *(const float4*)(A + (size_t)(bm0 + r) * K + k0 + c4);
            split2pack(v.x, v.y, &Ah[r * 40 + c4],     &Al[r * 40 + c4]);
            split2pack(v.z, v.w, &Ah[r * 40 + c4 + 2], &Al[r * 40 + c4 + 2]);
        }
        // W chunk 32x64: 512 float4
        #pragma unroll
        for (int it = 0; it < 2; it++) {
            int fid = tid + it * 256;
            int r = fid >> 4, c4 = (fid & 15) << 2;
            float4 v = *(const float4*)(W + (size_t)(k0 + r) * N + bn0 + c4);
            split2pack(v.x, v.y, &Wh[r * 72 + c4],     &Wl[r * 72 + c4]);
            split2pack(v.z, v.w, &Wh[r * 72 + c4 + 2], &Wl[r * 72 + c4 + 2]);
        }
        __syncthreads();

        uint32_t ahf[2][4], alf[2][4];
        #pragma unroll
        for (int ks2 = 0; ks2 < 2; ks2++) {
            int off = (w * 16 + (l & 7) + ((l >> 3) & 1) * 8) * 40
                      + ks2 * 16 + ((l >> 4) & 1) * 8;
            ldmx4(ahf[ks2][0], ahf[ks2][1], ahf[ks2][2], ahf[ks2][3], smem_u32(&Ah[off]));
            ldmx4(alf[ks2][0], alf[ks2][1], alf[ks2][2], alf[ks2][3], smem_u32(&Al[off]));
        }
        #pragma unroll
        for (int ks2 = 0; ks2 < 2; ks2++) {
            #pragma unroll
            for (int np = 0; np < 4; np++) {
                int off = (ks2 * 16 + ((l >> 3) & 1) * 8 + (l & 7)) * 72
                          + np * 16 + ((l >> 4) & 1) * 8;
                uint32_t wh0, wh1, wh2, wh3, wl0, wl1, wl2, wl3;
                ldmx4t(wh0, wh1, wh2, wh3, smem_u32(&Wh[off]));
                ldmx4t(wl0, wl1, wl2, wl3, smem_u32(&Wl[off]));
                mma16816(acc[2 * np],     ahf[ks2], wh0, wh1);
                mma16816(acc[2 * np],     ahf[ks2], wl0, wl1);
                mma16816(acc[2 * np],     alf[ks2], wh0, wh1);
                mma16816(acc[2 * np + 1], ahf[ks2], wh2, wh3);
                mma16816(acc[2 * np + 1], ahf[ks2], wl2, wl3);
                mma16816(acc[2 * np + 1], alf[ks2], wh2, wh3);
            }
        }
    }

    const int g = l >> 2, j2 = (l & 3) * 2;
    if (MODE == 0) {
        // n in [bn0, bn0+64): section fixed per CTA column tile
        int sect = bn0 >> 7;  // 0=q 1=k 2=v
        __nv_bfloat16 *dh, *dl;
        float mul;
        if (sect == 0)      { dh = g_qh; dl = g_ql; mul = SC2; }
        else if (sect == 1) { dh = g_kh; dl = g_kl; mul = 1.f; }
        else                { dh = g_vh; dl = g_vl; mul = 1.f; }
        #pragma unroll
        for (int nt = 0; nt < 8; nt++) {
            int n = bn0 + nt * 8 + j2;
            int col = n & 127;
            float b0 = bias[n], b1 = bias[n + 1];
            int r0 = bm0 + w * 16 + g;
            split2pack((acc[nt][0] + b0) * mul, (acc[nt][1] + b1) * mul,
                       dh + (size_t)r0 * CE + col, dl + (size_t)r0 * CE + col);
            split2pack((acc[nt][2] + b0) * mul, (acc[nt][3] + b1) * mul,
                       dh + (size_t)(r0 + 8) * CE + col, dl + (size_t)(r0 + 8) * CE + col);
        }
    } else {
        #pragma unroll
        for (int nt = 0; nt < 8; nt++) {
            int n = bn0 + nt * 8 + j2;
            float b0 = bias[n], b1 = bias[n + 1];
            float* p0 = Cp + (size_t)(bm0 + w * 16 + g) * N + n;
            float* p1 = Cp + (size_t)(bm0 + w * 16 + 8 + g) * N + n;
            *(float2*)p0 = make_float2(acc[nt][0] + b0, acc[nt][1] + b1);
            *(float2*)p1 = make_float2(acc[nt][2] + b0, acc[nt][3] + b1);
        }
    }
}

// ---------------------------------------------------------------------------
// Flash attention. 128 threads (4 warps x 32 query rows = 128-row Q tile),
// KV tile 64. Q fragments direct from global; K/V via cp.async double buffer.
// Epilogue writes fp32 g_y (feeds unchanged gemm<1>).
// ---------------------------------------------------------------------------
__global__ __launch_bounds__(128, 2) void attn_mma()
{
    __shared__ __nv_bfloat16 sm[2][4][64 * 40];  // [stage][kh,kl,vh,vl]

    const int tid = threadIdx.x;
    const int w   = tid >> 5;
    const int l   = tid & 31;
    const int qt  = 15 - blockIdx.x;  // heavy tiles first
    const int hh  = blockIdx.y;
    const int b   = blockIdx.z;
    const int qr0 = qt * 128;
    const int bT  = b * T_;
    const int hoff = hh * HD;
    const int nkv = 2 * qt + 2;

    // Q fragments straight from global (a-frag layout)
    uint32_t qhf[2][2][4], qlf[2][2][4];
    {
        int r = l >> 2, c2 = (l & 3) * 2;
        #pragma unroll
        for (int s = 0; s < 2; s++)
            #pragma unroll
            for (int ks2 = 0; ks2 < 2; ks2++) {
                size_t p = (size_t)(bT + qr0 + w * 32 + s * 16 + r) * CE
                           + hoff + ks2 * 16 + c2;
                qhf[s][ks2][0] = *(const uint32_t*)(g_qh + p);
                qhf[s][ks2][1] = *(const uint32_t*)(g_qh + p + 8 * CE);
                qhf[s][ks2][2] = *(const uint32_t*)(g_qh + p + 8);
                qhf[s][ks2][3] = *(const uint32_t*)(g_qh + p + 8 * CE + 8);
                qlf[s][ks2][0] = *(const uint32_t*)(g_ql + p);
                qlf[s][ks2][1] = *(const uint32_t*)(g_ql + p + 8 * CE);
                qlf[s][ks2][2] = *(const uint32_t*)(g_ql + p + 8);
                qlf[s][ks2][3] = *(const uint32_t*)(g_ql + p + 8 * CE + 8);
            }
    }

    auto prefetch = [&](int st, int kt) {
        int kn0 = kt * 64;
        #pragma unroll
        for (int it = 0; it < 8; it++) {
            const int arr = it >> 1;
            int sub = tid + (it & 1) * 128;
            int row = sub >> 2, j = sub & 3;
            const __nv_bfloat16* gp =
                (arr == 0) ? g_kh : (arr == 1) ? g_kl : (arr == 2) ? g_vh : g_vl;
            const __nv_bfloat16* src = gp + (size_t)(bT + kn0 + row) * CE + hoff + j * 8;
            cp16(smem_u32(&sm[st][arr][row * 40 + j * 8]), src);
        }
        asm volatile("cp.async.commit_group;" ::: "memory");
    };

    auto softmax_update = [&](float (&s)[8][4], float* m2, float* li, float (&o)[4][4]) {
        float mx0 = -1e30f, mx1 = -1e30f;
        #pragma unroll
        for (int nt = 0; nt < 8; nt++) {
            mx0 = fmaxf(mx0, fmaxf(s[nt][0], s[nt][1]));
            mx1 = fmaxf(mx1, fmaxf(s[nt][2], s[nt][3]));
        }
        mx0 = fmaxf(mx0, __shfl_xor_sync(0xffffffffu, mx0, 1));
        mx0 = fmaxf(mx0, __shfl_xor_sync(0xffffffffu, mx0, 2));
        mx1 = fmaxf(mx1, __shfl_xor_sync(0xffffffffu, mx1, 1));
        mx1 = fmaxf(mx1, __shfl_xor_sync(0xffffffffu, mx1, 2));
        float mn0 = fmaxf(m2[0], mx0), mn1 = fmaxf(m2[1], mx1);
        float al0 = ex2f(m2[0] - mn0), al1 = ex2f(m2[1] - mn1);
        m2[0] = mn0; m2[1] = mn1;
        float rs0 = 0.f, rs1 = 0.f;
        #pragma unroll
        for (int nt = 0; nt < 8; nt++) {
            s[nt][0] = ex2f(s[nt][0] - mn0);
            s[nt][1] = ex2f(s[nt][1] - mn0);
            s[nt][2] = ex2f(s[nt][2] - mn1);
            s[nt][3] = ex2f(s[nt][3] - mn1);
            rs0 += s[nt][0] + s[nt][1];
            rs1 += s[nt][2] + s[nt][3];
        }
        rs0 += __shfl_xor_sync(0xffffffffu, rs0, 1);
        rs0 += __shfl_xor_sync(0xffffffffu, rs0, 2);
        rs1 += __shfl_xor_sync(0xffffffffu, rs1, 1);
        rs1 += __shfl_xor_sync(0xffffffffu, rs1, 2);
        li[0] = li[0] * al0 + rs0;
        li[1] = li[1] * al1 + rs1;
        #pragma unroll
        for (int nt = 0; nt < 4; nt++) {
            o[nt][0] *= al0; o[nt][1] *= al0;
            o[nt][2] *= al1; o[nt][3] *= al1;
        }
    };

    float m2[4] = {-1e30f, -1e30f, -1e30f, -1e30f};
    float li[4] = {0.f, 0.f, 0.f, 0.f};
    float o0[4][4], o1[4][4];
    #pragma unroll
    for (int i = 0; i < 4; i++)
        #pragma unroll
        for (int j = 0; j < 4; j++) { o0[i][j] = 0.f; o1[i][j] = 0.f; }

    prefetch(0, 0);

    for (int kt = 0; kt < nkv; kt++) {
        const int kn0 = kt * 64;
        const int st = kt & 1;
        if (kt + 1 < nkv) {
            prefetch(st ^ 1, kt + 1);
            asm volatile("cp.async.wait_group 1;" ::: "memory");
        } else {
            asm volatile("cp.async.wait_group 0;" ::: "memory");
        }
        __syncthreads();

        if (kn0 <= qr0 + w * 32 + 31) {  // warp has unmasked work
            const __nv_bfloat16* KhS = sm[st][0];
            const __nv_bfloat16* KlS = sm[st][1];
            const __nv_bfloat16* VhS = sm[st][2];
            const __nv_bfloat16* VlS = sm[st][3];

            float s0[8][4], s1[8][4];
            #pragma unroll
            for (int i = 0; i < 8; i++)
                #pragma unroll
                for (int j = 0; j < 4; j++) { s0[i][j] = 0.f; s1[i][j] = 0.f; }

            // ---- S = Q @ K^T (K frags shared by both strips) ----
            #pragma unroll
            for (int ks2 = 0; ks2 < 2; ks2++) {
                #pragma unroll
                for (int np = 0; np < 4; np++) {
                    int off = (np * 16 + ((l >> 4) & 1) * 8 + (l & 7)) * 40
                              + ks2 * 16 + ((l >> 3) & 1) * 8;
                    uint32_t kh0, kh1, kh2, kh3, kl0, kl1, kl2, kl3;
                    ldmx4(kh0, kh1, kh2, kh3, smem_u32(KhS + off));
                    ldmx4(kl0, kl1, kl2, kl3, smem_u32(KlS + off));
                    mma16816(s0[2 * np],     qhf[0][ks2], kh0, kh1);
                    mma16816(s0[2 * np],     qhf[0][ks2], kl0, kl1);
                    mma16816(s0[2 * np],     qlf[0][ks2], kh0, kh1);
                    mma16816(s0[2 * np + 1], qhf[0][ks2], kh2, kh3);
                    mma16816(s0[2 * np + 1], qhf[0][ks2], kl2, kl3);
                    mma16816(s0[2 * np + 1], qlf[0][ks2], kh2, kh3);
                    mma16816(s1[2 * np],     qhf[1][ks2], kh0, kh1);
                    mma16816(s1[2 * np],     qhf[1][ks2], kl0, kl1);
                    mma16816(s1[2 * np],     qlf[1][ks2], kh0, kh1);
                    mma16816(s1[2 * np + 1], qhf[1][ks2], kh2, kh3);
                    mma16816(s1[2 * np + 1], qhf[1][ks2], kl2, kl3);
                    mma16816(s1[2 * np + 1], qlf[1][ks2], kh2, kh3);
                }
            }

            // ---- causal mask ----
            if (kn0 + 63 > qr0 + w * 32) {
                int r0 = qr0 + w * 32 + (l >> 2);
                #pragma unroll
                for (int nt = 0; nt < 8; nt++) {
                    int c = kn0 + nt * 8 + (l & 3) * 2;
                    if (c > r0)          s0[nt][0] = -1e30f;
                    if (c + 1 > r0)      s0[nt][1] = -1e30f;
                    if (c > r0 + 8)      s0[nt][2] = -1e30f;
                    if (c + 1 > r0 + 8)  s0[nt][3] = -1e30f;
                    if (c > r0 + 16)     s1[nt][0] = -1e30f;
                    if (c + 1 > r0 + 16) s1[nt][1] = -1e30f;
                    if (c > r0 + 24)     s1[nt][2] = -1e30f;
                    if (c + 1 > r0 + 24) s1[nt][3] = -1e30f;
                }
            }

            softmax_update(s0, &m2[0], &li[0], o0);
            softmax_update(s1, &m2[2], &li[2], o1);

            // ---- O += P @ V (V frags shared by both strips; 3-term hi/lo) ----
            #pragma unroll
            for (int kk = 0; kk < 4; kk++) {
                uint32_t a0[4], a1[4], a0l[4], a1l[4];
                a0[0]  = packbf(s0[2 * kk][0],     s0[2 * kk][1]);
                a0[1]  = packbf(s0[2 * kk][2],     s0[2 * kk][3]);
                a0[2]  = packbf(s0[2 * kk + 1][0], s0[2 * kk + 1][1]);
                a0[3]  = packbf(s0[2 * kk + 1][2], s0[2 * kk + 1][3]);
                a0l[0] = packbf(bfres(s0[2 * kk][0]),     bfres(s0[2 * kk][1]));
                a0l[1] = packbf(bfres(s0[2 * kk][2]),     bfres(s0[2 * kk][3]));
                a0l[2] = packbf(bfres(s0[2 * kk + 1][0]), bfres(s0[2 * kk + 1][1]));
                a0l[3] = packbf(bfres(s0[2 * kk + 1][2]), bfres(s0[2 * kk + 1][3]));
                a1[0]  = packbf(s1[2 * kk][0],     s1[2 * kk][1]);
                a1[1]  = packbf(s1[2 * kk][2],     s1[2 * kk][3]);
                a1[2]  = packbf(s1[2 * kk + 1][0], s1[2 * kk + 1][1]);
                a1[3]  = packbf(s1[2 * kk + 1][2], s1[2 * kk + 1][3]);
                a1l[0] = packbf(bfres(s1[2 * kk][0]),     bfres(s1[2 * kk][1]));
                a1l[1] = packbf(bfres(s1[2 * kk][2]),     bfres(s1[2 * kk][3]));
                a1l[2] = packbf(bfres(s1[2 * kk + 1][0]), bfres(s1[2 * kk + 1][1]));
                a1l[3] = packbf(bfres(s1[2 * kk + 1][2]), bfres(s1[2 * kk + 1][3]));
                #pragma unroll
                for (int np = 0; np < 2; np++) {
                    int off = (kk * 16 + ((l >> 3) & 1) * 8 + (l & 7)) * 40
                              + np * 16 + ((l >> 4) & 1) * 8;
                    uint32_t vh0, vh1, vh2, vh3, vl0, vl1, vl2, vl3;
                    ldmx4t(vh0, vh1, vh2, vh3, smem_u32(VhS + off));
                    ldmx4t(vl0, vl1, vl2, vl3, smem_u32(VlS + off));
                    mma16816(o0[2 * np],     a0,  vh0, vh1);
                    mma16816(o0[2 * np],     a0,  vl0, vl1);
                    mma16816(o0[2 * np],     a0l, vh0, vh1);
                    mma16816(o0[2 * np + 1], a0,  vh2, vh3);
                    mma16816(o0[2 * np + 1], a0,  vl2, vl3);
                    mma16816(o0[2 * np + 1], a0l, vh2, vh3);
                    mma16816(o1[2 * np],     a1,  vh0, vh1);
                    mma16816(o1[2 * np],     a1,  vl0, vl1);
                    mma16816(o1[2 * np],     a1l, vh0, vh1);
                    mma16816(o1[2 * np + 1], a1,  vh2, vh3);
                    mma16816(o1[2 * np + 1], a1,  vl2, vl3);
                    mma16816(o1[2 * np + 1], a1l, vh2, vh3);
                }
            }
        }
        __syncthreads();
    }

    // ---- epilogue: normalize, write fp32 y ----
    #pragma unroll
    for (int s = 0; s < 2; s++) {
        float (&o)[4][4] = s ? o1 : o0;
        #pragma unroll
        for (int g = 0; g < 2; g++) {
            float inv = 1.f / li[s * 2 + g];
            int row = qr0 + w * 32 + s * 16 + g * 8 + (l >> 2);
            size_t yb = (size_t)(bT + row) * CE + hoff;
            #pragma unroll
            for (int nt = 0; nt < 4; nt++) {
                int d = nt * 8 + (l & 3) * 2;
                *(float2*)(g_y + yb + d) =
                    make_float2(o[nt][g * 2] * inv, o[nt][g * 2 + 1] * inv);
            }
        }
    }
}

// ---------------------------------------------------------------------------
extern "C" void kernel_launch(void* const* d_in, const int* in_sizes, int n_in,
                              void* d_out, int out_size)
{
    const float* x      = (const float*)d_in[0];
    const float* w_qkv  = (const float*)d_in[1];
    const float* b_qkv  = (const float*)d_in[2];
    const float* w_proj = (const float*)d_in[3];
    const float* b_proj = (const float*)d_in[4];
    float* out = (float*)d_out;

    // 1) qkv projection -> g_q/g_k/g_v hi/lo (q pre-scaled), split fused
    gemm_mma<0><<<dim3(NTOK / 128, QKVS / 64), 256>>>(x, w_qkv, b_qkv, nullptr, QKVS);

    // 2) attention -> g_y (fp32)
    attn_mma<<<dim3(T_ / 128, NH, B_), 128>>>();

    // 3) out = g_y @ w_proj + b_proj
    gemm_mma<1><<<dim3(NTOK / 128, CE / 64), 256>>>(nullptr, w_proj, b_proj, out, CE);
}